// round 13
// baseline (speedup 1.0000x reference)
#include <cuda_runtime.h>
#include <math.h>

// S4D real SSM, v7: 3-kernel chunked scan, kernel-boundary sync ONLY.
//   precompute: per-state constants (all float; args are tiny exponents)
//   passA:      per-chunk aggregates v_k (zero-init recurrence over the tile)
//   passC:      h0(k) = fold_{j<k} (h = dc*h + v_j)  [L2-hot loads, no sync],
//               then the output recurrence + 8-lane butterfly + direct STG.
// No atomics, no fences, no spinning anywhere.

#define LEN 4096
#define CH  512
#define S   64
#define NC  32
#define LC  128
#define CS  (CH*S)
#define DTF (1.0f/4096.0f)

#define NPK 4              // f32x2 pairs per lane (8 states)
#define SPL 8              // states per lane
#define CPW 4              // channels per warp
#define CPB 32             // channels per block
#define NG  (CH/CPB)       // 16 channel groups

typedef unsigned long long ull;

__device__ float g_a [CS];      // exp(A*dt)
__device__ float g_cb[CS];      // C * Bd
__device__ float g_dc[CS];      // exp(A*dt*LC) (chunk decay)
__device__ float g_v [NC*CS];   // chunk aggregates

// ---- packed f32x2 helpers (Blackwell FFMA2, PTX-only) ---------------------
__device__ __forceinline__ ull pack2(float x, float y) {
    ull r; asm("mov.b64 %0, {%1, %2};" : "=l"(r) : "f"(x), "f"(y)); return r;
}
__device__ __forceinline__ ull fma2(ull a, ull b, ull c) {
    ull d; asm("fma.rn.f32x2 %0, %1, %2, %3;" : "=l"(d) : "l"(a), "l"(b), "l"(c)); return d;
}
__device__ __forceinline__ ull mul2(ull a, ull b) {
    ull d; asm("mul.rn.f32x2 %0, %1, %2;" : "=l"(d) : "l"(a), "l"(b)); return d;
}
__device__ __forceinline__ float hsum2(ull v) {
    float lo, hi; asm("mov.b64 {%0, %1}, %2;" : "=f"(lo), "=f"(hi) : "l"(v));
    return lo + hi;
}

// ---------------------------------------------------------------- precompute
__global__ void precompute_k(const float* __restrict__ lognegA,
                             const float* __restrict__ B,
                             const float* __restrict__ C)
{
    int i = blockIdx.x * blockDim.x + threadIdx.x;
    if (i >= CS) return;
    float A  = -__expf(lognegA[i]);          // in [-64, -1] here; fast exp ok
    float ad = A * DTF;                      // tiny negative exponent
    float Bd = expm1f(ad) / A * B[i];        // cancellation-safe
    g_a [i] = __expf(ad);
    g_cb[i] = C[i] * Bd;
    g_dc[i] = __expf(ad * (float)LC);
}

// ---------------------------------------------------------------- pass A
// grid (NC, NG), block 256. Lane owns 8 states (4 f32x2 pairs) of one channel.
__global__ __launch_bounds__(256, 4)
void passA_k(const float* __restrict__ x)
{
    __shared__ ull sx[LC][CPB];          // packed {x,x} tile, 32 KB
    const int k     = blockIdx.x;
    const int cbase = blockIdx.y * CPB;
    const int tid   = threadIdx.x;
    const int w     = tid >> 5;
    const int lane  = tid & 31;
    const int g     = lane >> 3;
    const int q     = lane & 7;
    const int l0    = k * LC;

    #pragma unroll 4
    for (int i = tid; i < LC * CPB / 4; i += 256) {
        int lr = i >> 3, c4 = (i & 7) << 2;
        float4 v4 = *reinterpret_cast<const float4*>(x + (l0 + lr) * CH + cbase + c4);
        sx[lr][c4 + 0] = pack2(v4.x, v4.x);
        sx[lr][c4 + 1] = pack2(v4.y, v4.y);
        sx[lr][c4 + 2] = pack2(v4.z, v4.z);
        sx[lr][c4 + 3] = pack2(v4.w, v4.w);
    }
    __syncthreads();

    const int c     = cbase + w * CPW + g;
    const int sbase = c * S + q * SPL;
    const int chl   = w * CPW + g;

    ull a[NPK];
    const ull* aP = reinterpret_cast<const ull*>(g_a + sbase);
    #pragma unroll
    for (int t = 0; t < NPK; t++) a[t] = aP[t];

    ull v[NPK] = {0ull, 0ull, 0ull, 0ull};
    #pragma unroll 8
    for (int l = 0; l < LC; l++) {
        ull xx = sx[l][chl];
        #pragma unroll
        for (int t = 0; t < NPK; t++) v[t] = fma2(a[t], v[t], xx);
    }

    ull* vP = reinterpret_cast<ull*>(g_v + k * CS + sbase);
    #pragma unroll
    for (int t = 0; t < NPK; t++) vP[t] = v[t];
}

// ---------------------------------------------------------------- pass C
__global__ __launch_bounds__(256, 4)
void passC_k(const float* __restrict__ x, float* __restrict__ y)
{
    __shared__ ull sx[LC][CPB];          // packed {x,x} tile, 32 KB
    const int k     = blockIdx.x;
    const int cbase = blockIdx.y * CPB;
    const int tid   = threadIdx.x;
    const int w     = tid >> 5;
    const int lane  = tid & 31;
    const int g     = lane >> 3;
    const int q     = lane & 7;
    const int l0    = k * LC;

    #pragma unroll 4
    for (int i = tid; i < LC * CPB / 4; i += 256) {
        int lr = i >> 3, c4 = (i & 7) << 2;
        float4 v4 = *reinterpret_cast<const float4*>(x + (l0 + lr) * CH + cbase + c4);
        sx[lr][c4 + 0] = pack2(v4.x, v4.x);
        sx[lr][c4 + 1] = pack2(v4.y, v4.y);
        sx[lr][c4 + 2] = pack2(v4.z, v4.z);
        sx[lr][c4 + 3] = pack2(v4.w, v4.w);
    }
    __syncthreads();

    const int c     = cbase + w * CPW + g;
    const int sbase = c * S + q * SPL;
    const int chl   = w * CPW + g;

    ull a[NPK];
    const ull* aP = reinterpret_cast<const ull*>(g_a + sbase);
    #pragma unroll
    for (int t = 0; t < NPK; t++) a[t] = aP[t];

    // ---- h0 for this chunk: fold the (already materialized) aggregates.
    // All loads are independent of the fold value -> ptxas batches them;
    // g_v (4 MB) is L2-resident after passA.
    ull h[NPK] = {0ull, 0ull, 0ull, 0ull};
    if (k > 0) {
        ull dc[NPK];
        const ull* dP = reinterpret_cast<const ull*>(g_dc + sbase);
        #pragma unroll
        for (int t = 0; t < NPK; t++) dc[t] = dP[t];
        #pragma unroll 4
        for (int j = 0; j < k; j++) {
            const ull* vj = reinterpret_cast<const ull*>(g_v + j * CS + sbase);
            ull v0 = __ldcg(vj + 0), v1 = __ldcg(vj + 1);
            ull v2 = __ldcg(vj + 2), v3 = __ldcg(vj + 3);
            h[0] = fma2(dc[0], h[0], v0);
            h[1] = fma2(dc[1], h[1], v1);
            h[2] = fma2(dc[2], h[2], v2);
            h[3] = fma2(dc[3], h[3], v3);
        }
    }

    // ---- output recurrence from h0
    ull cb[NPK];
    const ull* cbP = reinterpret_cast<const ull*>(g_cb + sbase);
    #pragma unroll
    for (int t = 0; t < NPK; t++) cb[t] = cbP[t];

    #pragma unroll 2
    for (int r = 0; r < LC / 8; r++) {
        float p[8];
        #pragma unroll
        for (int j = 0; j < 8; j++) {
            ull xx = sx[r * 8 + j][chl];
            #pragma unroll
            for (int t = 0; t < NPK; t++) h[t] = fma2(a[t], h[t], xx);
            ull acc = mul2(cb[0], h[0]);
            #pragma unroll
            for (int t = 1; t < NPK; t++) acc = fma2(cb[t], h[t], acc);
            p[j] = hsum2(acc);
        }
        // 3-stage register-halving butterfly over the 8-lane team:
        // afterwards lane q holds the finished output for step r*8+q
        #pragma unroll
        for (int d = 4; d >= 1; d >>= 1) {
            #pragma unroll
            for (int m = 0; m < d; m++) {
                bool  hi   = (q & d) != 0;
                float send = hi ? p[m] : p[m + d];
                float got  = __shfl_xor_sync(0xffffffffu, send, d);
                p[m] = (hi ? p[m + d] : p[m]) + got;
            }
        }
        y[(l0 + r * 8 + q) * CH + c] = p[0];
    }
}

// ---------------------------------------------------------------- launch
extern "C" void kernel_launch(void* const* d_in, const int* in_sizes, int n_in,
                              void* d_out, int out_size)
{
    const float* x       = (const float*)d_in[0];
    const float* lognegA = (const float*)d_in[1];
    const float* B       = (const float*)d_in[2];
    const float* C       = (const float*)d_in[3];
    float*       y       = (float*)d_out;

    precompute_k<<<CS / 256, 256>>>(lognegA, B, C);
    dim3 grid(NC, NG);
    passA_k<<<grid, 256>>>(x);
    passC_k<<<grid, 256>>>(x, y);
}